// round 6
// baseline (speedup 1.0000x reference)
#include <cuda_runtime.h>
#include <cuda_bf16.h>

// CharEmb fused kernel, R5: f32x2 packing + t-split for occupancy.
//
// Semantics (raw .view): x[e,c] = table[ids[e>>1]][(e&1)*32 + c].
// e-pair packing: acc2 lanes = (even-e sum, odd-e sum) via fma.rn.f32x2.
//
// R4 was register-limited (104 regs -> occ 24%, issue 50%). R5 splits the
// 30 t-positions across two 128-thread groups (block=256): each thread keeps
// only 15 packed accumulators (30 regs), then a smem max-reduce combines
// halves. Same total FMA2 work, ~2x occupancy.

#define NWORDS 16384
#define C_LEN  32
#define E_DIM  64
#define E2_DIM 32
#define F_DIM  128
#define T_OUT  30
#define T_HALF 15
#define W2SZ   (E2_DIM * 3 * F_DIM)   // 12288 u64 = 96 KB

typedef unsigned long long u64;

__device__ u64 g_wt2[W2SZ];   // [(e2*3+k)][f] : packed (w[f][2e2][k], w[f][2e2+1][k])

#define FMA2(acc, a, b) \
    asm("fma.rn.f32x2 %0, %1, %2, %0;" : "+l"(acc) : "l"(a), "l"(b))

__global__ __launch_bounds__(256) void transpose_w_kernel(
    const float* __restrict__ w)   // [128][64][3]
{
    int idx = blockIdx.x * blockDim.x + threadIdx.x;
    if (idx < W2SZ) {
        int j  = idx >> 7;       // e2*3 + k
        int f  = idx & 127;
        int e2 = j / 3;
        int k  = j - e2 * 3;
        float2 v = make_float2(w[f * 192 + (2 * e2)     * 3 + k],
                               w[f * 192 + (2 * e2 + 1) * 3 + k]);
        g_wt2[idx] = *reinterpret_cast<u64*>(&v);
    }
}

// Conv over one t-half. H = 0 -> t in [0,15), columns c in [0,17);
// H = 1 -> t in [15,30), columns c in [14,32). All bounds compile-time.
template<int H>
__device__ __forceinline__ void conv_half(
    const ulonglong2* __restrict__ row2base,
    const u64* __restrict__ wtf,
    u64 acc2[T_HALF])
{
    constexpr int TB = H * T_HALF;        // 0 or 15
    constexpr int Q0 = TB / 2;            // 0 or 7 (q covers c = 2q, 2q+1)

    #pragma unroll 4
    for (int e2 = 0; e2 < E2_DIM; ++e2) {
        u64 w0 = __ldg(wtf + (e2 * 3 + 0) * F_DIM);
        u64 w1 = __ldg(wtf + (e2 * 3 + 1) * F_DIM);
        u64 w2 = __ldg(wtf + (e2 * 3 + 2) * F_DIM);
        const ulonglong2* row2 = row2base + e2 * (C_LEN / 2);

        #pragma unroll
        for (int q = Q0; q < Q0 + 9; ++q) {
            ulonglong2 X = row2[q];
            const int l0 = 2 * q     - TB;   // local t-index base for column c0
            const int l1 = 2 * q + 1 - TB;
            if (l0 >= 0 && l0 <= T_HALF - 1)          FMA2(acc2[l0],     w0, X.x);
            if (l0 - 1 >= 0 && l0 - 1 <= T_HALF - 1)  FMA2(acc2[l0 - 1], w1, X.x);
            if (l0 - 2 >= 0 && l0 - 2 <= T_HALF - 1)  FMA2(acc2[l0 - 2], w2, X.x);
            if (l1 >= 0 && l1 <= T_HALF - 1)          FMA2(acc2[l1],     w0, X.y);
            if (l1 - 1 >= 0 && l1 - 1 <= T_HALF - 1)  FMA2(acc2[l1 - 1], w1, X.y);
            if (l1 - 2 >= 0 && l1 - 2 <= T_HALF - 1)  FMA2(acc2[l1 - 2], w2, X.y);
        }
    }
}

__global__ __launch_bounds__(256, 4) void charemb_kernel(
    const int*   __restrict__ ids,     // [NWORDS, 32]
    const float* __restrict__ table,   // [101, 64]
    const float* __restrict__ bias,    // [128]
    float*       __restrict__ out)     // [NWORDS, 128]
{
    __shared__ __align__(16) float2 sx2[E2_DIM * C_LEN];  // 8 KB
    __shared__ float red[2][F_DIM];                       // 1 KB

    const int n  = blockIdx.x;
    const int th = threadIdx.x;
    const int f  = th & 127;
    const int h  = th >> 7;           // t-half: 0 or 1

    // ---- Phase 1: gather. x[2e2][c] = table[id[e2]][c],
    //      x[2e2+1][c] = table[id[e2]][c+32] ----
    const int* idn = ids + n * C_LEN;
    #pragma unroll
    for (int j = 0; j < (E2_DIM * C_LEN) / 256; ++j) {   // 4 iters
        int p  = th + j * 256;
        int e2 = p >> 5;           // char index
        int c  = p & 31;           // conv position
        const float* row = table + idn[e2] * E_DIM;
        sx2[p] = make_float2(row[c], row[c + 32]);
    }
    __syncthreads();

    // ---- Phase 2: packed conv over this thread's t-half ----
    u64 acc2[T_HALF];
    #pragma unroll
    for (int t = 0; t < T_HALF; ++t) acc2[t] = 0ull;

    const u64* wtf = g_wt2 + f;
    const ulonglong2* row2base = reinterpret_cast<const ulonglong2*>(sx2);

    if (h == 0) conv_half<0>(row2base, wtf, acc2);
    else        conv_half<1>(row2base, wtf, acc2);

    // ---- Phase 3: per-half max (horizontal lo+hi), then combine ----
    float m = -__FLT_MAX__;
    #pragma unroll
    for (int t = 0; t < T_HALF; ++t) {
        u64 v = acc2[t];
        float lo = __int_as_float((int)(v & 0xffffffffull));
        float hi = __int_as_float((int)(v >> 32));
        m = fmaxf(m, lo + hi);
    }
    red[h][f] = m;
    __syncthreads();

    if (h == 0)
        out[n * F_DIM + f] = fmaxf(red[0][f], red[1][f]) + bias[f];
}

extern "C" void kernel_launch(void* const* d_in, const int* in_sizes, int n_in,
                              void* d_out, int out_size) {
    const int*   ids   = (const int*)  d_in[0];
    const float* table = (const float*)d_in[1];
    const float* w     = (const float*)d_in[2];
    const float* bias  = (const float*)d_in[3];
    float* out = (float*)d_out;

    transpose_w_kernel<<<(W2SZ + 255) / 256, 256>>>(w);
    charemb_kernel<<<NWORDS, 256>>>(ids, table, bias, out);
}

// round 10
// speedup vs baseline: 1.5753x; 1.5753x over previous
#include <cuda_runtime.h>
#include <cuda_bf16.h>
#include <cstdint>

// CharEmb R9: warp-level mma.sync (bf16, split-precision) im2col GEMM
// + fused max-pool. tcgen05 is unavailable (harness PTX target is plain
// sm_103, no 'a' suffix) — mma.sync.m16n8k16.bf16 is baseline sm_80+ PTX
// and runs on the same tensor pipe via HMMA.
//
// Semantics: x_w[e,c] = table[ids[w][e>>1]][(e&1)*32 + c]  (raw .view)
// D[t,f] = sum_kk A[t,kk]*B[kk,f], kk=e*3+k, B[kk,f]=w[f*192+kk]
// out[w,f] = max_{t<30} D[t,f] + bias[f]
//
// Per word: M=32 (rows 30,31 padded+masked), N=128, K=192.
// Split bf16: v=hi+lo; D = Ah*Bh + Al*Bh + Ah*Bl (rel err ~1e-5).
// B fragments precomputed in mma register layout (hi+lo, 96 KB, L1-resident).
// A fragments built per k-step from fp32 smem (stride-33 padded gather).

#define NWORDS 16384
#define F_DIM  128
#define KSTEPS 12          // 192 / 16
#define SXS    33          // padded smem row stride (floats)

typedef unsigned long long u64;

// B fragments: [img(2)][ks(12)][ntile(16)][lane(32)] as u64 (2 regs packed)
#define BFRAG_U64_PER_IMG (KSTEPS * 16 * 32)   // 6144
__device__ __align__(16) u64 g_Bfrag[2 * BFRAG_U64_PER_IMG];

__device__ __forceinline__ void mma_bf16(float* d, const uint32_t* a,
                                         uint32_t b0, uint32_t b1) {
    asm volatile(
        "mma.sync.aligned.m16n8k16.row.col.f32.bf16.bf16.f32 "
        "{%0,%1,%2,%3}, {%4,%5,%6,%7}, {%8,%9}, {%0,%1,%2,%3};"
        : "+f"(d[0]), "+f"(d[1]), "+f"(d[2]), "+f"(d[3])
        : "r"(a[0]), "r"(a[1]), "r"(a[2]), "r"(a[3]), "r"(b0), "r"(b1));
}

// hi = bf16x2(va,vb) (low half = va); lo = bf16x2 of residuals
__device__ __forceinline__ void split2(float va, float vb,
                                       uint32_t& hi, uint32_t& lo) {
    __nv_bfloat162 h2 = __float22bfloat162_rn(make_float2(va, vb));
    float2 hf = __bfloat1622float2(h2);
    __nv_bfloat162 l2 = __float22bfloat162_rn(make_float2(va - hf.x, vb - hf.y));
    hi = *reinterpret_cast<uint32_t*>(&h2);
    lo = *reinterpret_cast<uint32_t*>(&l2);
}

// ---------- prep: B fragments in mma layout ----------
// For k-step ks, ntile nt: B frag reg r holds B[k,n] pairs at
// k = ks*16 + 2*tig + 8r (+1), n = nt*8 + gid. B[kk,f] = w[f*192 + kk].
__global__ __launch_bounds__(256) void prep_b_kernel(const float* __restrict__ w) {
    int idx = blockIdx.x * blockDim.x + threadIdx.x;
    if (idx >= KSTEPS * 16 * 32) return;
    int lane = idx & 31;
    int nt   = (idx >> 5) & 15;
    int ks   = idx >> 9;
    int tig = lane & 3, gid = lane >> 2;
    int f = nt * 8 + gid;

    uint32_t h[2], l[2];
    #pragma unroll
    for (int r = 0; r < 2; ++r) {
        int k0 = ks * 16 + 2 * tig + 8 * r;
        split2(w[f * 192 + k0], w[f * 192 + k0 + 1], h[r], l[r]);
    }
    u64 hv = ((u64)h[1] << 32) | h[0];
    u64 lv = ((u64)l[1] << 32) | l[0];
    int o = (ks * 16 + nt) * 32 + lane;
    g_Bfrag[o] = hv;
    g_Bfrag[BFRAG_U64_PER_IMG + o] = lv;
}

// ---------- main ----------
__global__ __launch_bounds__(128) void charemb_kernel(
    const int*   __restrict__ ids,     // [NWORDS, 32]
    const float* __restrict__ table,   // [101, 64]
    const float* __restrict__ bias,    // [128]
    float*       __restrict__ out)     // [NWORDS, 128]
{
    __shared__ float sxf[64 * SXS];    // x_w[e][c], padded
    __shared__ float red[F_DIM];

    const int n    = blockIdx.x;
    const int tid  = threadIdx.x;
    const int wid  = tid >> 5;
    const int lane = tid & 31;
    const int tig  = lane & 3;
    const int gid  = lane >> 2;

    // ---- gather x: sxf[e][c] = table[id[e>>1]][(e&1)*32 + c] ----
    const int* idn = ids + n * 32;
    #pragma unroll
    for (int j = 0; j < 16; ++j) {
        int p = tid + j * 128;
        int e = p >> 5, c = p & 31;
        sxf[e * SXS + c] = __ldg(table + __ldg(idn + (e >> 1)) * 64 + (e & 1) * 32 + c);
    }
    __syncthreads();

    // accumulators: d[mt][ntl][4]
    float d[2][4][4];
    #pragma unroll
    for (int mt = 0; mt < 2; ++mt)
        #pragma unroll
        for (int l = 0; l < 4; ++l)
            #pragma unroll
            for (int r = 0; r < 4; ++r) d[mt][l][r] = 0.0f;

    const u64* bfr = g_Bfrag;

    for (int ks = 0; ks < KSTEPS; ++ks) {
        // 4 kk columns for this lane
        int kk0 = ks * 16 + 2 * tig;
        int e0 = kk0 / 3,       dk0 = kk0 - 3 * e0;
        int e1 = (kk0 + 1) / 3, dk1 = (kk0 + 1) - 3 * e1;
        int e8 = (kk0 + 8) / 3, dk8 = (kk0 + 8) - 3 * e8;
        int e9 = (kk0 + 9) / 3, dk9 = (kk0 + 9) - 3 * e9;

        // B fragments (hi + lo), coalesced LDG.64, L1-resident
        u64 bh[4], bl[4];
        #pragma unroll
        for (int l = 0; l < 4; ++l) {
            int o = (ks * 16 + (wid * 4 + l)) * 32 + lane;
            bh[l] = __ldg(bfr + o);
            bl[l] = __ldg(bfr + BFRAG_U64_PER_IMG + o);
        }

        #pragma unroll
        for (int mt = 0; mt < 2; ++mt) {
            int t0 = mt * 16 + gid;
            int t1 = t0 + 8;
            // clamp c to 31 for padded rows (t=30,31), masked in epilogue
            int c00 = min(t0 + dk0, 31), c01 = min(t0 + dk1, 31);
            int c10 = min(t1 + dk0, 31), c11 = min(t1 + dk1, 31);
            int c08 = min(t0 + dk8, 31), c09 = min(t0 + dk9, 31);
            int c18 = min(t1 + dk8, 31), c19 = min(t1 + dk9, 31);

            uint32_t ah[4], al[4];
            split2(sxf[e0 * SXS + c00], sxf[e1 * SXS + c01], ah[0], al[0]);
            split2(sxf[e0 * SXS + c10], sxf[e1 * SXS + c11], ah[1], al[1]);
            split2(sxf[e8 * SXS + c08], sxf[e9 * SXS + c09], ah[2], al[2]);
            split2(sxf[e8 * SXS + c18], sxf[e9 * SXS + c19], ah[3], al[3]);

            #pragma unroll
            for (int l = 0; l < 4; ++l) {
                uint32_t b0 = (uint32_t)bh[l], b1 = (uint32_t)(bh[l] >> 32);
                uint32_t c0 = (uint32_t)bl[l], c1 = (uint32_t)(bl[l] >> 32);
                mma_bf16(d[mt][l], ah, b0, b1);   // Ah*Bh
                mma_bf16(d[mt][l], al, b0, b1);   // Al*Bh
                mma_bf16(d[mt][l], ah, c0, c1);   // Ah*Bl
            }
        }
    }

    // ---- epilogue: max over t<30 per filter column ----
    // c-frag rows: c0,c1 -> row mt*16+gid ; c2,c3 -> row mt*16+gid+8.
    // Invalid rows: mt=1, +8 half, gid>=6 (rows 30,31).
    #pragma unroll
    for (int l = 0; l < 4; ++l) {
        float ve = fmaxf(d[0][l][0], d[0][l][2]);
        float vo = fmaxf(d[0][l][1], d[0][l][3]);
        ve = fmaxf(ve, d[1][l][0]);
        vo = fmaxf(vo, d[1][l][1]);
        if (gid < 6) {
            ve = fmaxf(ve, d[1][l][2]);
            vo = fmaxf(vo, d[1][l][3]);
        }
        #pragma unroll
        for (int s = 4; s < 32; s <<= 1) {
            ve = fmaxf(ve, __shfl_xor_sync(0xffffffffu, ve, s));
            vo = fmaxf(vo, __shfl_xor_sync(0xffffffffu, vo, s));
        }
        if (gid == 0) {
            int f = (wid * 4 + l) * 8 + 2 * tig;
            red[f]     = ve;
            red[f + 1] = vo;
        }
    }
    __syncthreads();

    out[n * F_DIM + tid] = red[tid] + __ldg(bias + tid);
}

extern "C" void kernel_launch(void* const* d_in, const int* in_sizes, int n_in,
                              void* d_out, int out_size) {
    const int*   ids   = (const int*)  d_in[0];
    const float* table = (const float*)d_in[1];
    const float* w     = (const float*)d_in[2];
    const float* bias  = (const float*)d_in[3];
    float* out = (float*)d_out;

    prep_b_kernel<<<(KSTEPS * 16 * 32 + 255) / 256, 256>>>(w);
    charemb_kernel<<<NWORDS, 128>>>(ids, table, bias, out);
}